// round 4
// baseline (speedup 1.0000x reference)
#include <cuda_runtime.h>
#include <cuda_bf16.h>

// Problem constants
#define B_TOT   32768
#define D1      120
#define HH      4
#define WW      2
#define NPER    960        // D1*HH*WW
#define D2      30         // after maxpool4
#define D3      10         // after maxpool3
#define P1N     240        // D2*HH*WW
#define P2N     80         // D3*HH*WW
#define NLATENT 100

// Output layout (float elements), concatenation of reference tuple:
//   z[B,100] | aug_xm[B,960] | aug_x_sd[B,1] | pool1_idx[B,240] | pool2_idx[B,80]
#define OFF_Z   ((size_t)0)
#define OFF_AXM ((size_t)B_TOT * NLATENT)                 // 3,276,800
#define OFF_ASD (OFF_AXM + (size_t)B_TOT * NPER)          // 34,734,080
#define OFF_P1  (OFF_ASD + (size_t)B_TOT)                 // 34,766,848
#define OFF_P2  (OFF_P1  + (size_t)B_TOT * P1N)           // 42,631,168

// depth stride in smem: 10 words -> warp octet groups hit banks {0,8,16,24}+0..7 (conflict-free)
#define XS_STRIDE 10

__global__ __launch_bounds__(256, 4)
void enc_kernel(const float* __restrict__ x1, const float* __restrict__ x2,
                const float* __restrict__ w1, const float* __restrict__ b1,
                const float* __restrict__ w2, const float* __restrict__ b2,
                const float* __restrict__ fcm1_w, const float* __restrict__ fcm1_b,
                const float* __restrict__ fc_w,   const float* __restrict__ fc_b,
                float* __restrict__ out)
{
    __shared__ float xs[D1 * XS_STRIDE];    // conv1 input, strided
    __shared__ float p1s[D2 * XS_STRIDE];   // pooled1, strided
    __shared__ float p2v[P2N];              // pooled2 (linear = reshape order)
    __shared__ float vec[12];               // [0..9]=ELU(fcm1), [10]=sigmoid(x2)
    __shared__ float w1s[21], w2s[21];
    __shared__ float fm1w[800], fm1b[10];
    __shared__ float fcw[1100], fcb[100];
    __shared__ float b1s_, b2s_;

    const int tid = threadIdx.x;
    const int b   = blockIdx.x;

    // ---- stage weights (L2-hot after first wave) ----
    if (tid < 21) { w1s[tid] = w1[tid]; w2s[tid] = w2[tid]; }
    for (int i = tid; i < 800;  i += 256) fm1w[i] = fcm1_w[i];
    for (int i = tid; i < 1100; i += 256) fcw[i]  = fc_w[i];
    if (tid < 100) fcb[tid] = fc_b[tid];
    if (tid < 10)  fm1b[tid] = fcm1_b[tid];
    if (tid == 254) { b1s_ = b1[0]; b2s_ = b2[0]; }

    // ---- stage x1 tile into smem (strided) + fused aug_xm identity copy ----
    const float4* xin = (const float4*)(x1 + (size_t)b * NPER);
    float4*       axm = (float4*)(out + OFF_AXM + (size_t)b * NPER);
    if (tid < 240) {
        float4 v = xin[tid];
        axm[tid] = v;                               // aug_xm = x1 (eval-mode identity)
        const int li = tid * 4;
        #pragma unroll
        for (int q = 0; q < 4; q++) {
            int idx = li + q;
            int d = idx >> 3, r = idx & 7;          // r = h*2+w
            xs[d * XS_STRIDE + r] = (&v.x)[q];
        }
    }
    if (tid == 255) {
        float xv = x2[b];
        out[OFF_ASD + b] = xv;                      // aug_x_sd = x2
        vec[10] = 1.0f / (1.0f + expf(-xv));        // sigmoid
    }
    __syncthreads();

    // ---- phase B: conv1(7,3,1) + bias + ReLU + maxpool_d(4) with argmax ----
    if (tid < P1N) {
        const int dp = tid >> 3, r8 = tid & 7;
        const int h = r8 >> 1, w = r8 & 1;
        const int d0 = dp * 4;
        float rwin[10][3];                          // depth window [d0-3, d0+6], h-1..h+1
        #pragma unroll
        for (int kd = 0; kd < 10; kd++) {
            const int d = d0 - 3 + kd;
            #pragma unroll
            for (int kh = 0; kh < 3; kh++) {
                const int hh = h - 1 + kh;
                rwin[kd][kh] = (d >= 0 && d < D1 && hh >= 0 && hh < HH)
                             ? xs[d * XS_STRIDE + hh * 2 + w] : 0.0f;
            }
        }
        float best = -1.0f; int bo = 0;             // ReLU vals >= 0 > -1: j=0 always seeds
        #pragma unroll
        for (int j = 0; j < 4; j++) {
            float acc = b1s_;
            #pragma unroll
            for (int a = 0; a < 7; a++)
                #pragma unroll
                for (int kh = 0; kh < 3; kh++)
                    acc = fmaf(rwin[j + a][kh], w1s[a * 3 + kh], acc);
            const float v = fmaxf(acc, 0.0f);
            if (v > best) { best = v; bo = j; }     // strict > == jnp.argmax first-max
        }
        p1s[dp * XS_STRIDE + r8] = best;
        out[OFF_P1 + (size_t)b * P1N + tid] =
            (float)(((d0 + bo) * HH + h) * WW + w);
    }
    __syncthreads();

    // ---- phase C: conv2(7,3,1) + bias + ReLU + maxpool_d(3) with argmax ----
    if (tid < P2N) {
        const int dp = tid >> 3, r8 = tid & 7;
        const int h = r8 >> 1, w = r8 & 1;
        const int d0 = dp * 3;
        float rwin[9][3];                           // depth window [d0-3, d0+5]
        #pragma unroll
        for (int kd = 0; kd < 9; kd++) {
            const int d = d0 - 3 + kd;
            #pragma unroll
            for (int kh = 0; kh < 3; kh++) {
                const int hh = h - 1 + kh;
                rwin[kd][kh] = (d >= 0 && d < D2 && hh >= 0 && hh < HH)
                             ? p1s[d * XS_STRIDE + hh * 2 + w] : 0.0f;
            }
        }
        float best = -1.0f; int bo = 0;
        #pragma unroll
        for (int j = 0; j < 3; j++) {
            float acc = b2s_;
            #pragma unroll
            for (int a = 0; a < 7; a++)
                #pragma unroll
                for (int kh = 0; kh < 3; kh++)
                    acc = fmaf(rwin[j + a][kh], w2s[a * 3 + kh], acc);
            const float v = fmaxf(acc, 0.0f);
            if (v > best) { best = v; bo = j; }
        }
        p2v[tid] = best;                            // linear: matches reshape(B,-1)
        out[OFF_P2 + (size_t)b * P2N + tid] =
            (float)(((d0 + bo) * HH + h) * WW + w);
    }
    __syncthreads();

    // ---- phase E: fcm1 (80 -> 10) + ELU ----
    if (tid < 10) {
        float acc = fm1b[tid];
        #pragma unroll
        for (int k = 0; k < 80; k++)
            acc = fmaf(p2v[k], fm1w[tid * 80 + k], acc);
        vec[tid] = (acc > 0.0f) ? acc : expm1f(acc);
    }
    __syncthreads();

    // ---- phase F: fc (11 -> 100) + BatchNorm eval (mean 0, var 1) ----
    if (tid < NLATENT) {
        float acc = fcb[tid];
        #pragma unroll
        for (int k = 0; k < 11; k++)
            acc = fmaf(vec[k], fcw[tid * 11 + k], acc);
        // z = y / sqrt(1 + 1e-5)
        out[OFF_Z + (size_t)b * NLATENT + tid] = acc * 0.9999950000374996f;
    }
}

extern "C" void kernel_launch(void* const* d_in, const int* in_sizes, int n_in,
                              void* d_out, int out_size)
{
    const float* x1     = (const float*)d_in[0];
    const float* x2     = (const float*)d_in[1];
    // d_in[2] = shifts (unused in eval), d_in[3] = nonzero_mask_xm (unused in eval)
    const float* w1     = (const float*)d_in[4];
    const float* b1     = (const float*)d_in[5];
    const float* w2     = (const float*)d_in[6];
    const float* b2     = (const float*)d_in[7];
    const float* fcm1_w = (const float*)d_in[8];
    const float* fcm1_b = (const float*)d_in[9];
    const float* fc_w   = (const float*)d_in[10];
    const float* fc_b   = (const float*)d_in[11];
    float* out = (float*)d_out;

    enc_kernel<<<B_TOT, 256>>>(x1, x2, w1, b1, w2, b2,
                               fcm1_w, fcm1_b, fc_w, fc_b, out);
}

// round 5
// speedup vs baseline: 1.3992x; 1.3992x over previous
#include <cuda_runtime.h>
#include <cuda_bf16.h>

// Problem constants
#define B_TOT   32768
#define D1      120
#define HH      4
#define WW      2
#define NPER    960        // D1*HH*WW
#define D2      30         // after maxpool4
#define P1N     240        // D2*HH*WW
#define P2N     80         // D3*HH*WW
#define NLATENT 100

// Output layout (float elements), concatenation of reference tuple:
//   z[B,100] | aug_xm[B,960] | aug_x_sd[B,1] | pool1_idx[B,240] | pool2_idx[B,80]
#define OFF_Z   ((size_t)0)
#define OFF_AXM ((size_t)B_TOT * NLATENT)
#define OFF_ASD (OFF_AXM + (size_t)B_TOT * NPER)
#define OFF_P1  (OFF_ASD + (size_t)B_TOT)
#define OFF_P2  (OFF_P1  + (size_t)B_TOT * P1N)

// smem depth stride = 10 words: octet groups land on banks {0,8,16,24}+r
#define XS 10

static __device__ __forceinline__ unsigned long long pk2(float x, float y) {
    unsigned long long r;
    asm("mov.b64 %0, {%1, %2};" : "=l"(r) : "f"(x), "f"(y));
    return r;
}
static __device__ __forceinline__ void upk2(unsigned long long v, float& x, float& y) {
    asm("mov.b64 {%0, %1}, %2;" : "=f"(x), "=f"(y) : "l"(v));
}
static __device__ __forceinline__ unsigned long long ffma2(
        unsigned long long a, unsigned long long b, unsigned long long c) {
    unsigned long long d;
    asm("fma.rn.f32x2 %0, %1, %2, %3;" : "=l"(d) : "l"(a), "l"(b), "l"(c));
    return d;
}

__global__ __launch_bounds__(128, 8)
void enc_kernel(const float* __restrict__ x1, const float* __restrict__ x2,
                const float* __restrict__ w1, const float* __restrict__ b1,
                const float* __restrict__ w2, const float* __restrict__ b2,
                const float* __restrict__ fcm1_w, const float* __restrict__ fcm1_b,
                const float* __restrict__ fc_w,   const float* __restrict__ fc_b,
                float* __restrict__ out)
{
    // +2 front pad so the (predicated-off but possibly speculated) hh=-1 address
    // stays in-bounds; depth halo of 3 zero rows each side kills d-predication.
    __shared__ float xsh[2 + 126 * XS];   // conv1 input, depths -3..122 at (d+3)
    __shared__ float p1sh[2 + 36 * XS];   // pooled1, depths -3..32 at (d+3)
    __shared__ float p2v[P2N];
    __shared__ float vec[11];             // [0..9]=ELU(fcm1), [10]=sigmoid(x2)
    __shared__ unsigned long long w1p[21], w2p[21];   // packed {w,w}
    __shared__ float fcws[1100];
    __shared__ float bb[2];

    const int tid = threadIdx.x;
    const int b   = blockIdx.x;

    // ---------------- Phase A: staging + fused aug copies ----------------
    if (tid < 21) {
        float a = w1[tid]; w1p[tid] = pk2(a, a);
        float c = w2[tid]; w2p[tid] = pk2(c, c);
    }
    if (tid == 121) { bb[0] = b1[0]; bb[1] = b2[0]; }
    for (int i = tid; i < 1100; i += 128) fcws[i] = fc_w[i];
    if (tid < 30) {          // zero depth halos (h range never needs halo rows)
        xsh[2 + tid] = 0.0f;          xsh[2 + 1230 + tid] = 0.0f;
        p1sh[2 + tid] = 0.0f;         p1sh[2 + 330 + tid] = 0.0f;
    }

    const float4* xin = (const float4*)(x1 + (size_t)b * NPER);
    float4*       axm = (float4*)(out + OFF_AXM + (size_t)b * NPER);
    {
        float4 v = xin[tid];
        axm[tid] = v;                                  // aug_xm = x1
        int d = tid >> 1, rb = (tid & 1) * 4;
        *(float2*)&xsh[2 + (d + 3) * XS + rb]     = make_float2(v.x, v.y);
        *(float2*)&xsh[2 + (d + 3) * XS + rb + 2] = make_float2(v.z, v.w);
    }
    if (tid < 112) {
        int i = tid + 128;
        float4 v = xin[i];
        axm[i] = v;
        int d = i >> 1, rb = (i & 1) * 4;
        *(float2*)&xsh[2 + (d + 3) * XS + rb]     = make_float2(v.x, v.y);
        *(float2*)&xsh[2 + (d + 3) * XS + rb + 2] = make_float2(v.z, v.w);
    }
    if (tid == 120) {
        float xv = x2[b];
        out[OFF_ASD + b] = xv;                         // aug_x_sd = x2
        vec[10] = 1.0f / (1.0f + expf(-xv));
    }
    __syncthreads();

    // ------- Phase B: conv1(7,3,1)+ReLU+maxpool4+argmax (packed f32x2) -------
    if (tid < 120) {
        const int dp = tid >> 2, h = tid & 3;
        const bool v0ok = (h > 0), v2ok = (h < 3);
        unsigned long long acc[4];
        {
            unsigned long long bp = pk2(bb[0], bb[0]);
            acc[0] = acc[1] = acc[2] = acc[3] = bp;
        }
        const float* xb = &xsh[2 + (4 * dp) * XS + (h - 1) * 2];
        #pragma unroll
        for (int kd = 0; kd < 10; kd++) {
            float2 a1 = *(const float2*)(xb + kd * XS + 2);
            float2 a0 = v0ok ? *(const float2*)(xb + kd * XS)     : make_float2(0.f, 0.f);
            float2 a2 = v2ok ? *(const float2*)(xb + kd * XS + 4) : make_float2(0.f, 0.f);
            unsigned long long u0 = pk2(a0.x, a0.y);
            unsigned long long u1 = pk2(a1.x, a1.y);
            unsigned long long u2 = pk2(a2.x, a2.y);
            #pragma unroll
            for (int j = 0; j < 4; j++) {
                const int a = kd - j;
                if (a < 0 || a > 6) continue;
                acc[j] = ffma2(u0, w1p[a * 3 + 0], acc[j]);
                acc[j] = ffma2(u1, w1p[a * 3 + 1], acc[j]);
                acc[j] = ffma2(u2, w1p[a * 3 + 2], acc[j]);
            }
        }
        float bx = -1.0f, by = -1.0f; int ix = 0, iy = 0;
        #pragma unroll
        for (int j = 0; j < 4; j++) {
            float px, py; upk2(acc[j], px, py);
            px = fmaxf(px, 0.0f); py = fmaxf(py, 0.0f);
            if (px > bx) { bx = px; ix = j; }       // strict > = first-max (argmax)
            if (py > by) { by = py; iy = j; }
        }
        *(float2*)&p1sh[2 + (dp + 3) * XS + h * 2] = make_float2(bx, by);
        float i0 = (float)(((4 * dp + ix) * HH + h) * WW + 0);
        float i1 = (float)(((4 * dp + iy) * HH + h) * WW + 1);
        *(float2*)&out[OFF_P1 + (size_t)b * P1N + dp * 8 + h * 2] = make_float2(i0, i1);
    }
    __syncthreads();

    // ------- Phase C: conv2(7,3,1)+ReLU+maxpool3+argmax -------
    if (tid < 40) {
        const int dp = tid >> 2, h = tid & 3;
        const bool v0ok = (h > 0), v2ok = (h < 3);
        unsigned long long acc[3];
        {
            unsigned long long bp = pk2(bb[1], bb[1]);
            acc[0] = acc[1] = acc[2] = bp;
        }
        const float* pb = &p1sh[2 + (3 * dp) * XS + (h - 1) * 2];
        #pragma unroll
        for (int kd = 0; kd < 9; kd++) {
            float2 a1 = *(const float2*)(pb + kd * XS + 2);
            float2 a0 = v0ok ? *(const float2*)(pb + kd * XS)     : make_float2(0.f, 0.f);
            float2 a2 = v2ok ? *(const float2*)(pb + kd * XS + 4) : make_float2(0.f, 0.f);
            unsigned long long u0 = pk2(a0.x, a0.y);
            unsigned long long u1 = pk2(a1.x, a1.y);
            unsigned long long u2 = pk2(a2.x, a2.y);
            #pragma unroll
            for (int j = 0; j < 3; j++) {
                const int a = kd - j;
                if (a < 0 || a > 6) continue;
                acc[j] = ffma2(u0, w2p[a * 3 + 0], acc[j]);
                acc[j] = ffma2(u1, w2p[a * 3 + 1], acc[j]);
                acc[j] = ffma2(u2, w2p[a * 3 + 2], acc[j]);
            }
        }
        float bx = -1.0f, by = -1.0f; int ix = 0, iy = 0;
        #pragma unroll
        for (int j = 0; j < 3; j++) {
            float px, py; upk2(acc[j], px, py);
            px = fmaxf(px, 0.0f); py = fmaxf(py, 0.0f);
            if (px > bx) { bx = px; ix = j; }
            if (py > by) { by = py; iy = j; }
        }
        *(float2*)&p2v[dp * 8 + h * 2] = make_float2(bx, by);
        float i0 = (float)(((3 * dp + ix) * HH + h) * WW + 0);
        float i1 = (float)(((3 * dp + iy) * HH + h) * WW + 1);
        *(float2*)&out[OFF_P2 + (size_t)b * P2N + dp * 8 + h * 2] = make_float2(i0, i1);
    }
    __syncthreads();

    // ------- Phase E: fcm1 (80->10) + ELU, 8 lanes per output, shuffle-reduce -------
    if (tid < 80) {
        const int j = tid >> 3, s = tid & 7;
        const float* wr = fcm1_w + j * 80 + s;
        float acc = 0.0f;
        #pragma unroll
        for (int i = 0; i < 10; i++)
            acc = fmaf(p2v[s + 8 * i], wr[8 * i], acc);
        unsigned m = __activemask();
        acc += __shfl_xor_sync(m, acc, 4);
        acc += __shfl_xor_sync(m, acc, 2);
        acc += __shfl_xor_sync(m, acc, 1);
        if (s == 0) {
            float t = acc + fcm1_b[j];
            vec[j] = (t > 0.0f) ? t : expm1f(t);
        }
    }
    __syncthreads();

    // ------- Phase F: fc (11->100) + BatchNorm eval -------
    if (tid < NLATENT) {
        float acc = fc_b[tid];
        #pragma unroll
        for (int k = 0; k < 11; k++)
            acc = fmaf(vec[k], fcws[tid * 11 + k], acc);   // stride 11: bank-conflict-free
        out[OFF_Z + (size_t)b * NLATENT + tid] = acc * 0.9999950000374996f;
    }
}

extern "C" void kernel_launch(void* const* d_in, const int* in_sizes, int n_in,
                              void* d_out, int out_size)
{
    const float* x1     = (const float*)d_in[0];
    const float* x2     = (const float*)d_in[1];
    // d_in[2]=shifts, d_in[3]=nonzero_mask_xm : unused in eval-mode forward
    const float* w1     = (const float*)d_in[4];
    const float* b1     = (const float*)d_in[5];
    const float* w2     = (const float*)d_in[6];
    const float* b2     = (const float*)d_in[7];
    const float* fcm1_w = (const float*)d_in[8];
    const float* fcm1_b = (const float*)d_in[9];
    const float* fc_w   = (const float*)d_in[10];
    const float* fc_b   = (const float*)d_in[11];
    float* out = (float*)d_out;

    enc_kernel<<<B_TOT, 128>>>(x1, x2, w1, b1, w2, b2,
                               fcm1_w, fcm1_b, fc_w, fc_b, out);
}

// round 6
// speedup vs baseline: 1.8327x; 1.3098x over previous
#include <cuda_runtime.h>
#include <cuda_bf16.h>

// Problem constants
#define B_TOT   32768
#define NPER    960        // 120*4*2
#define P1N     240
#define P2N     80
#define NLATENT 100

// Output layout (float elements):
//   z[B,100] | aug_xm[B,960] | aug_x_sd[B,1] | pool1_idx[B,240] | pool2_idx[B,80]
#define OFF_Z   ((size_t)0)
#define OFF_AXM ((size_t)B_TOT * NLATENT)
#define OFF_ASD (OFF_AXM + (size_t)B_TOT * NPER)
#define OFF_P1  (OFF_ASD + (size_t)B_TOT)
#define OFF_P2  (OFF_P1  + (size_t)B_TOT * P1N)

typedef unsigned long long u64;

// Pre-swizzled GEMV weights (filled by prep_kernel every call)
__device__ float g_fm1X[800];    // [i<10][tid<80] = fcm1_w[(tid>>3)*80 + (tid&7) + 8i]
__device__ float g_fcX[1100];    // [k<11][t<100]  = fc_w[t*11 + k]

// Conv weights in constant memory (uniform access -> LDCU, zero L1 traffic)
__constant__ float c_w1[21];
__constant__ float c_w2[21];
__constant__ float c_b[2];

static __device__ __forceinline__ u64 pk2(float x, float y) {
    u64 r; asm("mov.b64 %0, {%1, %2};" : "=l"(r) : "f"(x), "f"(y)); return r;
}
static __device__ __forceinline__ void upk2(u64 v, float& x, float& y) {
    asm("mov.b64 {%0, %1}, %2;" : "=f"(x), "=f"(y) : "l"(v));
}
static __device__ __forceinline__ u64 ffma2(u64 a, u64 b, u64 c) {
    u64 d; asm("fma.rn.f32x2 %0, %1, %2, %3;" : "=l"(d) : "l"(a), "l"(b), "l"(c));
    return d;
}
// XOR swizzle on 16B-group index: spreads depth-strided accesses over bank groups
static __device__ __forceinline__ int SWZ(int g) { return g ^ ((g >> 3) & 7); }

__global__ void prep_kernel(const float* __restrict__ fcm1_w,
                            const float* __restrict__ fc_w) {
    const int t = threadIdx.x;
    for (int idx = t; idx < 800; idx += 128) {
        int i = idx / 80, r = idx - i * 80;
        int j = r >> 3, s = r & 7;
        g_fm1X[idx] = fcm1_w[j * 80 + s + 8 * i];
    }
    for (int idx = t; idx < 1100; idx += 128) {
        int k = idx / 100, j = idx - k * 100;
        g_fcX[idx] = fc_w[j * 11 + k];
    }
}

#define WP1(a,kh) pk2(c_w1[(a)*3+(kh)], c_w1[(a)*3+(kh)])
#define WP2(a,kh) pk2(c_w2[(a)*3+(kh)], c_w2[(a)*3+(kh)])

__global__ __launch_bounds__(128, 6)
void enc_kernel(const float* __restrict__ x1, const float* __restrict__ x2,
                const float* __restrict__ fcm1_b, const float* __restrict__ fc_b,
                float* __restrict__ out)
{
    // Rows of 8 floats (= 2 float4 groups), depth-halo of 3 zero rows each side.
    __shared__ float4 xsh4[256];   // 126 rows (d+3 in 0..125) -> groups 0..251 (+swizzle pad)
    __shared__ float4 p1sh4[72];   // 36 rows  (d+3 in 0..35)  -> groups 0..71
    __shared__ float  p2v[P2N];
    __shared__ float  vec[11];     // [0..9]=ELU(fcm1), [10]=sigmoid(x2)

    const int tid = threadIdx.x;
    const int b   = blockIdx.x;

    // ---------------- Phase A: input staging + fused aug copies ----------------
    if (tid < 12) {      // zero depth-halo rows (groups 0..5 and 246..251)
        int g = (tid < 6) ? tid : (240 + tid);
        xsh4[SWZ(g)] = make_float4(0.f, 0.f, 0.f, 0.f);
        p1sh4[SWZ((tid < 6) ? tid : (60 + tid))] = make_float4(0.f, 0.f, 0.f, 0.f);
    }
    const float4* xin = (const float4*)(x1 + (size_t)b * NPER);
    float4*       axm = (float4*)(out + OFF_AXM + (size_t)b * NPER);
    {
        float4 v = xin[tid];
        axm[tid] = v;                           // aug_xm = x1 (eval identity)
        xsh4[SWZ(tid + 6)] = v;                 // group g = i + 6
    }
    if (tid < 112) {
        int i = tid + 128;
        float4 v = xin[i];
        axm[i] = v;
        xsh4[SWZ(i + 6)] = v;
    }
    if (tid == 120) {
        float xv = x2[b];
        out[OFF_ASD + b] = xv;                  // aug_x_sd = x2
        vec[10] = 1.0f / (1.0f + expf(-xv));
    }
    __syncthreads();

    // ------- Phase B: conv1(7,3,1)+ReLU+maxpool4+argmax -------
    // thread (dp, hp): dp in 0..29 pool group, hp selects h-pair {2hp, 2hp+1}
    if (tid < 60) {
        const int dp = tid >> 1, hp = tid & 1;
        const bool hs = (hp != 0);
        u64 acc[4][2];
        {
            u64 bi0 = pk2(c_b[0], c_b[0]);
            #pragma unroll
            for (int j = 0; j < 4; j++) { acc[j][0] = bi0; acc[j][1] = bi0; }
        }
        #pragma unroll
        for (int kd = 0; kd < 10; kd++) {
            const int r = 4 * dp + kd;                // halo row index
            float4 A  = xsh4[SWZ(2 * r)];
            float4 Bv = xsh4[SWZ(2 * r + 1)];
            u64 u0 = pk2(A.x, A.y),  u1 = pk2(A.z, A.w);
            u64 u2 = pk2(Bv.x, Bv.y), u3 = pk2(Bv.z, Bv.w);
            // W[m] = h-position (2hp-1+m); zero arms double as h-boundary padding
            u64 W0 = hs ? u1 : 0ULL;
            u64 W1 = hs ? u2 : u0;
            u64 W2 = hs ? u3 : u1;
            u64 W3 = hs ? 0ULL : u2;
            #pragma unroll
            for (int j = 0; j < 4; j++) {
                const int a = kd - j;
                if (a < 0 || a > 6) continue;
                acc[j][0] = ffma2(W0, WP1(a, 0), acc[j][0]);
                acc[j][0] = ffma2(W1, WP1(a, 1), acc[j][0]);
                acc[j][0] = ffma2(W2, WP1(a, 2), acc[j][0]);
                acc[j][1] = ffma2(W1, WP1(a, 0), acc[j][1]);
                acc[j][1] = ffma2(W2, WP1(a, 1), acc[j][1]);
                acc[j][1] = ffma2(W3, WP1(a, 2), acc[j][1]);
            }
        }
        float bv0 = -1.f, bv1 = -1.f, bv2 = -1.f, bv3 = -1.f;
        int   bi0 = 0, bi1 = 0, bi2 = 0, bi3 = 0;
        #pragma unroll
        for (int j = 0; j < 4; j++) {
            float p00, p01, p10, p11, v;
            upk2(acc[j][0], p00, p01); upk2(acc[j][1], p10, p11);
            v = fmaxf(p00, 0.f); if (v > bv0) { bv0 = v; bi0 = j; }  // strict > = first-max
            v = fmaxf(p01, 0.f); if (v > bv1) { bv1 = v; bi1 = j; }
            v = fmaxf(p10, 0.f); if (v > bv2) { bv2 = v; bi2 = j; }
            v = fmaxf(p11, 0.f); if (v > bv3) { bv3 = v; bi3 = j; }
        }
        p1sh4[SWZ(2 * (dp + 3) + hp)] = make_float4(bv0, bv1, bv2, bv3);
        const int h0 = 2 * hp, d0 = 4 * dp;
        float4 iv;
        iv.x = (float)(((d0 + bi0) * 4 + h0) * 2 + 0);
        iv.y = (float)(((d0 + bi1) * 4 + h0) * 2 + 1);
        iv.z = (float)(((d0 + bi2) * 4 + h0 + 1) * 2 + 0);
        iv.w = (float)(((d0 + bi3) * 4 + h0 + 1) * 2 + 1);
        *(float4*)&out[OFF_P1 + (size_t)b * P1N + dp * 8 + hp * 4] = iv;
    }
    __syncthreads();

    // ------- Phase C: conv2(7,3,1)+ReLU+maxpool3+argmax -------
    if (tid < 20) {
        const int dp = tid >> 1, hp = tid & 1;
        const bool hs = (hp != 0);
        u64 acc[3][2];
        {
            u64 bi0 = pk2(c_b[1], c_b[1]);
            #pragma unroll
            for (int j = 0; j < 3; j++) { acc[j][0] = bi0; acc[j][1] = bi0; }
        }
        #pragma unroll
        for (int t = 0; t < 9; t++) {
            const int r = 3 * dp + t;
            float4 A  = p1sh4[SWZ(2 * r)];
            float4 Bv = p1sh4[SWZ(2 * r + 1)];
            u64 u0 = pk2(A.x, A.y),  u1 = pk2(A.z, A.w);
            u64 u2 = pk2(Bv.x, Bv.y), u3 = pk2(Bv.z, Bv.w);
            u64 W0 = hs ? u1 : 0ULL;
            u64 W1 = hs ? u2 : u0;
            u64 W2 = hs ? u3 : u1;
            u64 W3 = hs ? 0ULL : u2;
            #pragma unroll
            for (int j = 0; j < 3; j++) {
                const int a = t - j;
                if (a < 0 || a > 6) continue;
                acc[j][0] = ffma2(W0, WP2(a, 0), acc[j][0]);
                acc[j][0] = ffma2(W1, WP2(a, 1), acc[j][0]);
                acc[j][0] = ffma2(W2, WP2(a, 2), acc[j][0]);
                acc[j][1] = ffma2(W1, WP2(a, 0), acc[j][1]);
                acc[j][1] = ffma2(W2, WP2(a, 1), acc[j][1]);
                acc[j][1] = ffma2(W3, WP2(a, 2), acc[j][1]);
            }
        }
        float bv0 = -1.f, bv1 = -1.f, bv2 = -1.f, bv3 = -1.f;
        int   bi0 = 0, bi1 = 0, bi2 = 0, bi3 = 0;
        #pragma unroll
        for (int j = 0; j < 3; j++) {
            float p00, p01, p10, p11, v;
            upk2(acc[j][0], p00, p01); upk2(acc[j][1], p10, p11);
            v = fmaxf(p00, 0.f); if (v > bv0) { bv0 = v; bi0 = j; }
            v = fmaxf(p01, 0.f); if (v > bv1) { bv1 = v; bi1 = j; }
            v = fmaxf(p10, 0.f); if (v > bv2) { bv2 = v; bi2 = j; }
            v = fmaxf(p11, 0.f); if (v > bv3) { bv3 = v; bi3 = j; }
        }
        *(float4*)&p2v[dp * 8 + hp * 4] = make_float4(bv0, bv1, bv2, bv3);
        const int h0 = 2 * hp, d0 = 3 * dp;
        float4 iv;
        iv.x = (float)(((d0 + bi0) * 4 + h0) * 2 + 0);
        iv.y = (float)(((d0 + bi1) * 4 + h0) * 2 + 1);
        iv.z = (float)(((d0 + bi2) * 4 + h0 + 1) * 2 + 0);
        iv.w = (float)(((d0 + bi3) * 4 + h0 + 1) * 2 + 1);
        *(float4*)&out[OFF_P2 + (size_t)b * P2N + dp * 8 + hp * 4] = iv;
    }
    __syncthreads();

    // ------- Phase E: fcm1 (80->10) + ELU, 8 lanes/output, coalesced weights -------
    if (tid < 80) {
        const int j = tid >> 3, s = tid & 7;
        float acc = 0.0f;
        #pragma unroll
        for (int i = 0; i < 10; i++)
            acc = fmaf(p2v[s + 8 * i], g_fm1X[80 * i + tid], acc);   // 128B/warp-instr
        unsigned m = __activemask();
        acc += __shfl_xor_sync(m, acc, 4);
        acc += __shfl_xor_sync(m, acc, 2);
        acc += __shfl_xor_sync(m, acc, 1);
        if (s == 0) {
            float t = acc + fcm1_b[j];
            vec[j] = (t > 0.0f) ? t : expm1f(t);
        }
    }
    __syncthreads();

    // ------- Phase F: fc (11->100) + BatchNorm eval -------
    if (tid < NLATENT) {
        float acc = fc_b[tid];
        #pragma unroll
        for (int k = 0; k < 11; k++)
            acc = fmaf(vec[k], g_fcX[k * 100 + tid], acc);           // coalesced
        out[OFF_Z + (size_t)b * NLATENT + tid] = acc * 0.9999950000374996f;
    }
}

extern "C" void kernel_launch(void* const* d_in, const int* in_sizes, int n_in,
                              void* d_out, int out_size)
{
    const float* x1     = (const float*)d_in[0];
    const float* x2     = (const float*)d_in[1];
    // d_in[2]=shifts, d_in[3]=nonzero_mask_xm : unused in eval-mode forward
    const float* w1     = (const float*)d_in[4];
    const float* b1     = (const float*)d_in[5];
    const float* w2     = (const float*)d_in[6];
    const float* b2     = (const float*)d_in[7];
    const float* fcm1_w = (const float*)d_in[8];
    const float* fcm1_b = (const float*)d_in[9];
    const float* fc_w   = (const float*)d_in[10];
    const float* fc_b   = (const float*)d_in[11];
    float* out = (float*)d_out;

    // D2D memcpy nodes: graph-capturable
    cudaMemcpyToSymbolAsync(c_w1, w1, 21 * sizeof(float), 0, cudaMemcpyDeviceToDevice, 0);
    cudaMemcpyToSymbolAsync(c_w2, w2, 21 * sizeof(float), 0, cudaMemcpyDeviceToDevice, 0);
    cudaMemcpyToSymbolAsync(c_b,  b1, sizeof(float), 0,             cudaMemcpyDeviceToDevice, 0);
    cudaMemcpyToSymbolAsync(c_b,  b2, sizeof(float), sizeof(float), cudaMemcpyDeviceToDevice, 0);

    prep_kernel<<<1, 128>>>(fcm1_w, fc_w);
    enc_kernel<<<B_TOT, 128>>>(x1, x2, fcm1_b, fc_b, out);
}